// round 2
// baseline (speedup 1.0000x reference)
#include <cuda_runtime.h>
#include <cstdint>

#define BATCH    65536
#define IN_FEAT  512
#define OUT_FEAT 256
#define EPS      1e-5f

#define BM       64
#define BK       32
#define NTHREADS 128
#define AS_STRIDE 68   // padded, multiple of 4 floats (16B aligned rows)

typedef unsigned long long u64;

__device__ __forceinline__ u64 pack2(float lo, float hi) {
    u64 r; asm("mov.b64 %0, {%1,%2};" : "=l"(r) : "f"(lo), "f"(hi)); return r;
}
__device__ __forceinline__ void unpack2(u64 v, float& lo, float& hi) {
    asm("mov.b64 {%0,%1}, %2;" : "=f"(lo), "=f"(hi) : "l"(v));
}
__device__ __forceinline__ u64 ffma2(u64 a, u64 b, u64 c) {
    u64 d; asm("fma.rn.f32x2 %0, %1, %2, %3;" : "=l"(d) : "l"(a), "l"(b), "l"(c)); return d;
}

__global__ __launch_bounds__(NTHREADS, 2)
void fused_lin_gn_min_kernel(const float* __restrict__ x,
                             const float* __restrict__ W,
                             const float* __restrict__ bias_linear,
                             const float* __restrict__ weight_gn,
                             const float* __restrict__ bias_gn,
                             const float* __restrict__ bias,
                             float* __restrict__ out)
{
    __shared__ float As[BK][AS_STRIDE];   // As[k][m]
    __shared__ float Bs[BK][OUT_FEAT];    // Bs[k][o]
    __shared__ float smin[BM];

    const int tid = threadIdx.x;
    const int tn  = tid & 15;        // 16 N-threads, 16 channels each
    const int tm  = tid >> 4;        // 8 M-threads, 8 rows each
    const int b0  = blockIdx.x * BM;
    const int cbase = tn * 16;

    // 8 rows x 8 f32x2 pairs (16 channels) accumulators
    u64 acc[8][8];
    #pragma unroll
    for (int i = 0; i < 8; i++)
        #pragma unroll
        for (int j = 0; j < 8; j++) acc[i][j] = 0ull;

    const float* xg = x + (size_t)b0 * IN_FEAT;

    for (int kt = 0; kt < IN_FEAT; kt += BK) {
        __syncthreads();
        // ---- load x tile: 64 rows x 32 k (coalesced: 8 lanes cover one 128B row-chunk)
        #pragma unroll
        for (int i = 0; i < 4; i++) {
            int idx = tid + i * NTHREADS;   // 0..511
            int r = idx >> 3;               // 0..63
            int c = idx & 7;                // 0..7 (float4 index within 32 k)
            float4 v = *(const float4*)(xg + (size_t)r * IN_FEAT + kt + c * 4);
            As[c*4+0][r] = v.x;
            As[c*4+1][r] = v.y;
            As[c*4+2][r] = v.z;
            As[c*4+3][r] = v.w;
        }
        // ---- load W tile: 256 o x 32 k, transposed into Bs[k][o]
        // lane pairs read 32B contiguous per o-row -> full 32B sector efficiency in L2
        #pragma unroll
        for (int i = 0; i < 16; i++) {
            int idx  = tid + i * NTHREADS;  // 0..2047
            int half = idx & 1;
            int pos  = idx >> 1;            // 0..1023
            int o    = pos & 255;
            int c    = ((pos >> 8) << 1) + half;   // 0..7
            float4 v = *(const float4*)(W + (size_t)o * IN_FEAT + kt + c * 4);
            Bs[c*4+0][o] = v.x;
            Bs[c*4+1][o] = v.y;
            Bs[c*4+2][o] = v.z;
            Bs[c*4+3][o] = v.w;
        }
        __syncthreads();

        // ---- compute
        #pragma unroll
        for (int kk = 0; kk < BK; kk++) {
            float4 a0 = *(const float4*)&As[kk][tm * 8];
            float4 a1 = *(const float4*)&As[kk][tm * 8 + 4];
            u64 a2[8];
            a2[0] = pack2(a0.x, a0.x); a2[1] = pack2(a0.y, a0.y);
            a2[2] = pack2(a0.z, a0.z); a2[3] = pack2(a0.w, a0.w);
            a2[4] = pack2(a1.x, a1.x); a2[5] = pack2(a1.y, a1.y);
            a2[6] = pack2(a1.z, a1.z); a2[7] = pack2(a1.w, a1.w);

            // adjacent channels form natural f32x2 pairs (little-endian: lo first)
            ulonglong2 bb0 = *(const ulonglong2*)&Bs[kk][cbase];
            ulonglong2 bb1 = *(const ulonglong2*)&Bs[kk][cbase + 4];
            ulonglong2 bb2 = *(const ulonglong2*)&Bs[kk][cbase + 8];
            ulonglong2 bb3 = *(const ulonglong2*)&Bs[kk][cbase + 12];
            u64 b2[8] = { bb0.x, bb0.y, bb1.x, bb1.y, bb2.x, bb2.y, bb3.x, bb3.y };

            #pragma unroll
            for (int m = 0; m < 8; m++)
                #pragma unroll
                for (int p = 0; p < 8; p++)
                    acc[m][p] = ffma2(a2[m], b2[p], acc[m][p]);
        }
    }

    // ---- epilogue: +bias_linear, GroupNorm (group size 32 = this thread + xor-1 partner),
    //      channel min across the 16 tn-lanes, all via shuffles.
    float4 blv0 = *(const float4*)(bias_linear + cbase);
    float4 blv1 = *(const float4*)(bias_linear + cbase + 4);
    float4 blv2 = *(const float4*)(bias_linear + cbase + 8);
    float4 blv3 = *(const float4*)(bias_linear + cbase + 12);
    float bl[16] = { blv0.x,blv0.y,blv0.z,blv0.w, blv1.x,blv1.y,blv1.z,blv1.w,
                     blv2.x,blv2.y,blv2.z,blv2.w, blv3.x,blv3.y,blv3.z,blv3.w };

    float4 wgv0 = *(const float4*)(weight_gn + cbase);
    float4 wgv1 = *(const float4*)(weight_gn + cbase + 4);
    float4 wgv2 = *(const float4*)(weight_gn + cbase + 8);
    float4 wgv3 = *(const float4*)(weight_gn + cbase + 12);
    float wg[16] = { wgv0.x,wgv0.y,wgv0.z,wgv0.w, wgv1.x,wgv1.y,wgv1.z,wgv1.w,
                     wgv2.x,wgv2.y,wgv2.z,wgv2.w, wgv3.x,wgv3.y,wgv3.z,wgv3.w };

    float4 bgv0 = *(const float4*)(bias_gn + cbase);
    float4 bgv1 = *(const float4*)(bias_gn + cbase + 4);
    float4 bgv2 = *(const float4*)(bias_gn + cbase + 8);
    float4 bgv3 = *(const float4*)(bias_gn + cbase + 12);
    float bg[16] = { bgv0.x,bgv0.y,bgv0.z,bgv0.w, bgv1.x,bgv1.y,bgv1.z,bgv1.w,
                     bgv2.x,bgv2.y,bgv2.z,bgv2.w, bgv3.x,bgv3.y,bgv3.z,bgv3.w };

    #pragma unroll
    for (int i = 0; i < 8; i++) {
        float hv[16];
        #pragma unroll
        for (int p = 0; p < 8; p++) {
            float lo, hi;
            unpack2(acc[i][p], lo, hi);
            hv[2*p]   = lo + bl[2*p];
            hv[2*p+1] = hi + bl[2*p+1];
        }
        float s = 0.f, sq = 0.f;
        #pragma unroll
        for (int j = 0; j < 16; j++) { s += hv[j]; sq += hv[j] * hv[j]; }
        s  += __shfl_xor_sync(0xffffffffu, s, 1);
        sq += __shfl_xor_sync(0xffffffffu, sq, 1);
        float mean = s * (1.0f / 32.0f);
        float var  = sq * (1.0f / 32.0f) - mean * mean;
        float rstd = rsqrtf(var + EPS);

        float mn = 3.4e38f;
        #pragma unroll
        for (int j = 0; j < 16; j++) {
            float g = (hv[j] - mean) * rstd * wg[j] + bg[j];
            mn = fminf(mn, g);
        }
        mn = fminf(mn, __shfl_xor_sync(0xffffffffu, mn, 1));
        mn = fminf(mn, __shfl_xor_sync(0xffffffffu, mn, 2));
        mn = fminf(mn, __shfl_xor_sync(0xffffffffu, mn, 4));
        mn = fminf(mn, __shfl_xor_sync(0xffffffffu, mn, 8));
        if (tn == 0) smin[tm * 8 + i] = mn;
    }
    __syncthreads();

    // ---- broadcast output: out[c*B + b] = min[b] + bias[c]
    const int bq = tid & 15;        // which float4 of the 64 rows
    const int cb = tid >> 4;        // starting channel
    float4 mv = *(const float4*)&smin[bq * 4];
    #pragma unroll 8
    for (int cc = cb; cc < OUT_FEAT; cc += 8) {
        float bc = __ldg(bias + cc);
        float4 o;
        o.x = mv.x + bc; o.y = mv.y + bc; o.z = mv.z + bc; o.w = mv.w + bc;
        *(float4*)(out + (size_t)cc * BATCH + b0 + bq * 4) = o;
    }
}

extern "C" void kernel_launch(void* const* d_in, const int* in_sizes, int n_in,
                              void* d_out, int out_size) {
    const float* x  = (const float*)d_in[0];
    const float* W  = (const float*)d_in[1];
    const float* bl = (const float*)d_in[2];
    const float* wg = (const float*)d_in[3];
    const float* bg = (const float*)d_in[4];
    const float* bs = (const float*)d_in[5];
    float* out = (float*)d_out;

    dim3 grid(BATCH / BM);
    dim3 block(NTHREADS);
    fused_lin_gn_min_kernel<<<grid, block>>>(x, W, bl, wg, bg, bs, out);
}

// round 3
// speedup vs baseline: 2.0773x; 2.0773x over previous
#include <cuda_runtime.h>
#include <cstdint>

#define BATCH    65536
#define IN_FEAT  512
#define OUT_FEAT 256
#define EPS      1e-5f

#define BM       64
#define BK       32
#define NTHREADS 128
#define AS_STRIDE 68   // padded row (floats), multiple of 4 for 16B-aligned LDS.128

typedef unsigned long long u64;

// Pre-transposed weights: Wt[k][o], k-major. 512 KB static device scratch.
__device__ float Wt[IN_FEAT * OUT_FEAT];

__global__ void transpose_w_kernel(const float* __restrict__ W) {
    int idx = blockIdx.x * blockDim.x + threadIdx.x;   // 0 .. 131071
    int o = idx >> 9;          // 0..255
    int k = idx & 511;         // 0..511  (coalesced read over k)
    Wt[(size_t)k * OUT_FEAT + o] = W[(size_t)o * IN_FEAT + k];
}

__device__ __forceinline__ u64 pack2(float lo, float hi) {
    u64 r; asm("mov.b64 %0, {%1,%2};" : "=l"(r) : "f"(lo), "f"(hi)); return r;
}
__device__ __forceinline__ void unpack2(u64 v, float& lo, float& hi) {
    asm("mov.b64 {%0,%1}, %2;" : "=f"(lo), "=f"(hi) : "l"(v));
}
__device__ __forceinline__ u64 ffma2(u64 a, u64 b, u64 c) {
    u64 d; asm("fma.rn.f32x2 %0, %1, %2, %3;" : "=l"(d) : "l"(a), "l"(b), "l"(c)); return d;
}

__global__ __launch_bounds__(NTHREADS, 2)
void fused_lin_gn_min_kernel(const float* __restrict__ x,
                             const float* __restrict__ bias_linear,
                             const float* __restrict__ weight_gn,
                             const float* __restrict__ bias_gn,
                             const float* __restrict__ bias,
                             float* __restrict__ out)
{
    __shared__ float As[BK][AS_STRIDE];   // As[k][m]
    __shared__ float Bs[BK][OUT_FEAT];    // Bs[k][o]
    __shared__ float smin[BM];

    const int tid = threadIdx.x;
    const int tn  = tid & 15;        // channel-quarter lane: owns ch j*64 + tn*4 + c
    const int tm  = tid >> 4;        // 8 M-threads, 8 rows each
    const int b0  = blockIdx.x * BM;

    // 8 rows x 8 f32x2 pairs (16 channels) accumulators
    u64 acc[8][8];
    #pragma unroll
    for (int i = 0; i < 8; i++)
        #pragma unroll
        for (int j = 0; j < 8; j++) acc[i][j] = 0ull;

    const float* xg = x + (size_t)b0 * IN_FEAT;

    for (int kt = 0; kt < IN_FEAT; kt += BK) {
        __syncthreads();
        // ---- load x tile: 64 rows x 32 k, transposed into As[k][m]
        #pragma unroll
        for (int i = 0; i < 4; i++) {
            int idx = tid + i * NTHREADS;   // 0..511
            int r = idx >> 3;               // 0..63
            int c = idx & 7;                // float4 index within the 32-k tile
            float4 v = *(const float4*)(xg + (size_t)r * IN_FEAT + kt + c * 4);
            As[c*4+0][r] = v.x;
            As[c*4+1][r] = v.y;
            As[c*4+2][r] = v.z;
            As[c*4+3][r] = v.w;
        }
        // ---- load W tile from pre-transposed Wt: contiguous LDG.128 -> STS.128
        #pragma unroll
        for (int i = 0; i < 16; i++) {
            int idx = tid + i * NTHREADS;   // 0..2047 (= 32 rows * 64 float4)
            int r  = idx >> 6;              // k row within tile
            int c4 = idx & 63;              // float4 column
            float4 v = *(const float4*)(Wt + (size_t)(kt + r) * OUT_FEAT + c4 * 4);
            *(float4*)&Bs[r][c4 * 4] = v;
        }
        __syncthreads();

        // ---- compute
        #pragma unroll
        for (int kk = 0; kk < BK; kk++) {
            float4 a0 = *(const float4*)&As[kk][tm * 8];
            float4 a1 = *(const float4*)&As[kk][tm * 8 + 4];
            u64 a2[8];
            a2[0] = pack2(a0.x, a0.x); a2[1] = pack2(a0.y, a0.y);
            a2[2] = pack2(a0.z, a0.z); a2[3] = pack2(a0.w, a0.w);
            a2[4] = pack2(a1.x, a1.x); a2[5] = pack2(a1.y, a1.y);
            a2[6] = pack2(a1.z, a1.z); a2[7] = pack2(a1.w, a1.w);

            // conflict-free: for each j, 16 lanes read contiguous 256B
            u64 b2[8];
            #pragma unroll
            for (int j = 0; j < 4; j++) {
                ulonglong2 bb = *(const ulonglong2*)&Bs[kk][j * 64 + tn * 4];
                b2[2*j]   = bb.x;   // channels j*64+tn*4 + {0,1}
                b2[2*j+1] = bb.y;   // channels j*64+tn*4 + {2,3}
            }

            #pragma unroll
            for (int m = 0; m < 8; m++)
                #pragma unroll
                for (int p = 0; p < 8; p++)
                    acc[m][p] = ffma2(a2[m], b2[p], acc[m][p]);
        }
    }

    // ---- epilogue: +bias_linear, GroupNorm, channel min, all via shuffles.
    // Thread channel c(j,c) = j*64 + tn*4 + c ; its group g = 2j + (tn>>3);
    // group members = same j across the tn-octet -> shfl_xor {1,2,4}.
    float bl[16], wg[16], bg[16];
    #pragma unroll
    for (int j = 0; j < 4; j++) {
        float4 v;
        v = *(const float4*)(bias_linear + j * 64 + tn * 4);
        bl[j*4+0]=v.x; bl[j*4+1]=v.y; bl[j*4+2]=v.z; bl[j*4+3]=v.w;
        v = *(const float4*)(weight_gn + j * 64 + tn * 4);
        wg[j*4+0]=v.x; wg[j*4+1]=v.y; wg[j*4+2]=v.z; wg[j*4+3]=v.w;
        v = *(const float4*)(bias_gn + j * 64 + tn * 4);
        bg[j*4+0]=v.x; bg[j*4+1]=v.y; bg[j*4+2]=v.z; bg[j*4+3]=v.w;
    }

    #pragma unroll
    for (int i = 0; i < 8; i++) {
        float hv[16];
        #pragma unroll
        for (int p = 0; p < 8; p++) {
            float lo, hi;
            unpack2(acc[i][p], lo, hi);
            int j = p >> 1;
            int base = j * 4 + (p & 1) * 2;
            hv[base]     = lo + bl[base];
            hv[base + 1] = hi + bl[base + 1];
        }
        // per-j (per-group-slice) partial stats over this thread's 4 channels
        float s[4], sq[4];
        #pragma unroll
        for (int j = 0; j < 4; j++) {
            float a = hv[j*4+0], b = hv[j*4+1], c = hv[j*4+2], d = hv[j*4+3];
            s[j]  = (a + b) + (c + d);
            sq[j] = (a*a + b*b) + (c*c + d*d);
        }
        // reduce over the 8-lane tn-octet (lane = (tm&1)*16 + tn; xor<=4 stays in octet)
        #pragma unroll
        for (int m = 1; m <= 4; m <<= 1) {
            #pragma unroll
            for (int j = 0; j < 4; j++) {
                s[j]  += __shfl_xor_sync(0xffffffffu, s[j],  m);
                sq[j] += __shfl_xor_sync(0xffffffffu, sq[j], m);
            }
        }
        float mn = 3.4e38f;
        #pragma unroll
        for (int j = 0; j < 4; j++) {
            float mean = s[j] * (1.0f / 32.0f);
            float var  = sq[j] * (1.0f / 32.0f) - mean * mean;
            float rstd = rsqrtf(var + EPS);
            #pragma unroll
            for (int c = 0; c < 4; c++) {
                float g = (hv[j*4+c] - mean) * rstd * wg[j*4+c] + bg[j*4+c];
                mn = fminf(mn, g);
            }
        }
        // min over all 16 tn lanes (xor 8 crosses octets - fine for global min)
        mn = fminf(mn, __shfl_xor_sync(0xffffffffu, mn, 1));
        mn = fminf(mn, __shfl_xor_sync(0xffffffffu, mn, 2));
        mn = fminf(mn, __shfl_xor_sync(0xffffffffu, mn, 4));
        mn = fminf(mn, __shfl_xor_sync(0xffffffffu, mn, 8));
        if (tn == 0) smin[tm * 8 + i] = mn;
    }
    __syncthreads();

    // ---- broadcast output: out[c*B + b] = min[b] + bias[c]
    const int bq = tid & 15;        // which float4 of the 64 rows
    const int cb = tid >> 4;        // starting channel
    float4 mv = *(const float4*)&smin[bq * 4];
    #pragma unroll 8
    for (int cc = cb; cc < OUT_FEAT; cc += 8) {
        float bc = __ldg(bias + cc);
        float4 o;
        o.x = mv.x + bc; o.y = mv.y + bc; o.z = mv.z + bc; o.w = mv.w + bc;
        *(float4*)(out + (size_t)cc * BATCH + b0 + bq * 4) = o;
    }
}

extern "C" void kernel_launch(void* const* d_in, const int* in_sizes, int n_in,
                              void* d_out, int out_size) {
    const float* x  = (const float*)d_in[0];
    const float* W  = (const float*)d_in[1];
    const float* bl = (const float*)d_in[2];
    const float* wg = (const float*)d_in[3];
    const float* bg = (const float*)d_in[4];
    const float* bs = (const float*)d_in[5];
    float* out = (float*)d_out;

    transpose_w_kernel<<<(IN_FEAT * OUT_FEAT) / 256, 256>>>(x ? (const float*)d_in[1] : nullptr);
    fused_lin_gn_min_kernel<<<BATCH / BM, NTHREADS>>>(x, bl, wg, bg, bs, out);
}

// round 5
// speedup vs baseline: 4.2813x; 2.0610x over previous
#include <cuda_runtime.h>
#include <cuda_bf16.h>
#include <cstdint>

#define BATCH    65536
#define IN_FEAT  512
#define OUT_FEAT 256
#define EPS      1e-5f

#define BM       64
#define KT       64
#define NKT      (IN_FEAT / KT)
#define NTHREADS 256

// ---- dynamic smem layout (bytes) ----
#define SM_BL      0        // bias_linear  (256 f)
#define SM_WGN     1024     // weight_gn
#define SM_BGN     2048     // bias_gn
#define SM_ROWMIN  3072     // 4 nwarps x 64 rows
#define SM_SMIN    4096     // 64 floats
#define SM_BUF     8192
#define OFF_AH     0        // 64 x 128B  (xh)
#define OFF_AL     8192     // 64 x 128B  (xl)
#define OFF_BH     16384    // 256 x 128B (Wh)
#define OFF_BL     49152    // 256 x 128B (Wl)
#define BUFSZ      81920
#define SM_TOTAL   (SM_BUF + 2 * BUFSZ)   // 172032

// pre-split weights, row-major [o][k]
__device__ __nv_bfloat16 Wh_g[OUT_FEAT * IN_FEAT];
__device__ __nv_bfloat16 Wl_g[OUT_FEAT * IN_FEAT];

__global__ void split_w_kernel(const float* __restrict__ W) {
    int i = blockIdx.x * blockDim.x + threadIdx.x;   // 0..131071
    float w = W[i];
    __nv_bfloat16 hi = __float2bfloat16(w);
    __nv_bfloat16 lo = __float2bfloat16(w - __bfloat162float(hi));
    Wh_g[i] = hi;
    Wl_g[i] = lo;
}

__device__ __forceinline__ uint32_t smem_u32(const void* p) {
    uint32_t a;
    asm("{ .reg .u64 t; cvta.to.shared.u64 t, %1; cvt.u32.u64 %0, t; }" : "=r"(a) : "l"(p));
    return a;
}
__device__ __forceinline__ void split2(float a, float b, uint32_t& h, uint32_t& l) {
    __nv_bfloat162 hb = __floats2bfloat162_rn(a, b);
    float2 hf = __bfloat1622float2(hb);
    __nv_bfloat162 lb = __floats2bfloat162_rn(a - hf.x, b - hf.y);
    h = *reinterpret_cast<uint32_t*>(&hb);
    l = *reinterpret_cast<uint32_t*>(&lb);
}
__device__ __forceinline__ void ldsm4(uint32_t* r, uint32_t addr) {
    asm volatile("ldmatrix.sync.aligned.m8n8.x4.shared.b16 {%0,%1,%2,%3}, [%4];"
                 : "=r"(r[0]), "=r"(r[1]), "=r"(r[2]), "=r"(r[3]) : "r"(addr));
}
__device__ __forceinline__ void mma16816(float* d, const uint32_t* a,
                                         uint32_t b0, uint32_t b1) {
    asm volatile(
        "mma.sync.aligned.m16n8k16.row.col.f32.bf16.bf16.f32 "
        "{%0,%1,%2,%3}, {%4,%5,%6,%7}, {%8,%9}, {%0,%1,%2,%3};"
        : "+f"(d[0]), "+f"(d[1]), "+f"(d[2]), "+f"(d[3])
        : "r"(a[0]), "r"(a[1]), "r"(a[2]), "r"(a[3]), "r"(b0), "r"(b1));
}
__device__ __forceinline__ void cp16(uint32_t dst, const void* src) {
    asm volatile("cp.async.cg.shared.global [%0], [%1], 16;" :: "r"(dst), "l"(src) : "memory");
}
__device__ __forceinline__ void cp_commit() { asm volatile("cp.async.commit_group;" ::: "memory"); }
__device__ __forceinline__ void cp_wait0()  { asm volatile("cp.async.wait_group 0;"  ::: "memory"); }

__global__ __launch_bounds__(NTHREADS, 1)
void fused_mma_kernel(const float* __restrict__ x,
                      const float* __restrict__ bias_linear,
                      const float* __restrict__ weight_gn,
                      const float* __restrict__ bias_gn,
                      const float* __restrict__ bias,
                      float* __restrict__ out)
{
    extern __shared__ char smem[];
    float* smf = reinterpret_cast<float*>(smem);
    const uint32_t sb = smem_u32(smem);

    const int tid = threadIdx.x;
    const int lid = tid & 31;
    const int wid = tid >> 5;
    const int mw  = wid & 1;       // M half   (rows mw*32)
    const int nw  = wid >> 1;      // N quarter (cols nw*64)
    const int l8  = lid & 7;
    const int sub = lid >> 3;
    const int b0  = blockIdx.x * BM;

    // stage epilogue consts
    smf[SM_BL  / 4 + tid] = bias_linear[tid];
    smf[SM_WGN / 4 + tid] = weight_gn[tid];
    smf[SM_BGN / 4 + tid] = bias_gn[tid];

    // ldmatrix per-thread address pieces (XOR-16B swizzle within 128B rows)
    const uint32_t a_off = (uint32_t)(mw * 32 + l8 + 8 * (sub & 1)) * 128;
    const uint32_t b_off = (uint32_t)(nw * 64 + l8 + 8 * (sub >> 1)) * 128;
    const uint32_t akh = (uint32_t)(sub >> 1);
    const uint32_t bkh = (uint32_t)(sub & 1);
    const uint32_t lx  = (uint32_t)l8 << 4;

    // x load/store indices: two 8-float chunks per thread per tile
    const int xr0 = tid >> 3;            // 0..31
    const int xc  = tid & 7;             // 8-float chunk
    const uint32_t xo0 = (uint32_t)xr0 * 128 + (uint32_t)((xc ^ (xr0 & 7)) << 4);
    const uint32_t xo1 = xo0 + 32 * 128; // rows +32 keep same (row&7)

    // W cp.async indices
    const int wr0 = tid >> 3;            // + j*32
    const int wc  = tid & 7;
    const uint32_t wswz = (uint32_t)((wc ^ (wr0 & 7)) << 4);

    const float* xg = x + (size_t)b0 * IN_FEAT;

    float d[2][8][4];
    #pragma unroll
    for (int i = 0; i < 2; i++)
        #pragma unroll
        for (int j = 0; j < 8; j++)
            #pragma unroll
            for (int k = 0; k < 4; k++) d[i][j][k] = 0.f;

    float4 xv[4];

    // ---------------- prologue: fill buffer 0 with tile 0 ----------------
    {
        const float* p0 = xg + (size_t)xr0 * IN_FEAT + xc * 8;
        const float* p1 = xg + (size_t)(xr0 + 32) * IN_FEAT + xc * 8;
        xv[0] = *(const float4*)p0;  xv[1] = *(const float4*)(p0 + 4);
        xv[2] = *(const float4*)p1;  xv[3] = *(const float4*)(p1 + 4);
        uint4 h, l;
        split2(xv[0].x, xv[0].y, h.x, l.x); split2(xv[0].z, xv[0].w, h.y, l.y);
        split2(xv[1].x, xv[1].y, h.z, l.z); split2(xv[1].z, xv[1].w, h.w, l.w);
        *(uint4*)(smem + SM_BUF + OFF_AH + xo0) = h;
        *(uint4*)(smem + SM_BUF + OFF_AL + xo0) = l;
        split2(xv[2].x, xv[2].y, h.x, l.x); split2(xv[2].z, xv[2].w, h.y, l.y);
        split2(xv[3].x, xv[3].y, h.z, l.z); split2(xv[3].z, xv[3].w, h.w, l.w);
        *(uint4*)(smem + SM_BUF + OFF_AH + xo1) = h;
        *(uint4*)(smem + SM_BUF + OFF_AL + xo1) = l;

        #pragma unroll
        for (int j = 0; j < 8; j++) {
            int row = wr0 + j * 32;
            uint32_t dsth = sb + SM_BUF + OFF_BH + (uint32_t)row * 128 + wswz;
            uint32_t dstl = sb + SM_BUF + OFF_BL + (uint32_t)row * 128 + wswz;
            cp16(dsth, Wh_g + (size_t)row * IN_FEAT + wc * 8);
            cp16(dstl, Wl_g + (size_t)row * IN_FEAT + wc * 8);
        }
        cp_commit();
        cp_wait0();
        __syncthreads();
    }

    // ---------------- main loop ----------------
    for (int kt = 0; kt < NKT; kt++) {
        const int p = kt & 1;
        const uint32_t bufb  = sb + SM_BUF + (uint32_t)p * BUFSZ;
        char*     nbufc = smem + SM_BUF + (p ^ 1) * BUFSZ;
        const uint32_t nbufb = sb + SM_BUF + (uint32_t)(p ^ 1) * BUFSZ;
        const bool more = (kt + 1 < NKT);

        // prefetch next x into regs + next W via cp.async (into free buffer)
        if (more) {
            const int kb = (kt + 1) * KT;
            const float* p0 = xg + (size_t)xr0 * IN_FEAT + kb + xc * 8;
            const float* p1 = xg + (size_t)(xr0 + 32) * IN_FEAT + kb + xc * 8;
            xv[0] = *(const float4*)p0;  xv[1] = *(const float4*)(p0 + 4);
            xv[2] = *(const float4*)p1;  xv[3] = *(const float4*)(p1 + 4);
            #pragma unroll
            for (int j = 0; j < 8; j++) {
                int row = wr0 + j * 32;
                cp16(nbufb + OFF_BH + (uint32_t)row * 128 + wswz,
                     Wh_g + (size_t)row * IN_FEAT + kb + wc * 8);
                cp16(nbufb + OFF_BL + (uint32_t)row * 128 + wswz,
                     Wl_g + (size_t)row * IN_FEAT + kb + wc * 8);
            }
            cp_commit();
        }

        // ---- compute: 3 terms x 4 k16-steps x (2 m-blocks x 8 n-blocks) ----
        const uint32_t abase[3] = { bufb + OFF_AH, bufb + OFF_AH, bufb + OFF_AL };
        const uint32_t bbase[3] = { bufb + OFF_BH, bufb + OFF_BL, bufb + OFF_BH };
        #pragma unroll
        for (int t = 0; t < 3; t++) {
            const uint32_t Ab = abase[t] + a_off;
            const uint32_t Bb = bbase[t] + b_off;
            #pragma unroll
            for (int ks = 0; ks < 4; ks++) {
                const uint32_t ak = (((uint32_t)(2 * ks) + akh) << 4) ^ lx;
                const uint32_t bk = (((uint32_t)(2 * ks) + bkh) << 4) ^ lx;
                uint32_t a0[4], a1[4];
                ldsm4(a0, Ab + ak);
                ldsm4(a1, Ab + 2048 + ak);
                uint32_t bf[4][4];
                #pragma unroll
                for (int pr = 0; pr < 4; pr++) ldsm4(bf[pr], Bb + pr * 2048 + bk);
                #pragma unroll
                for (int pr = 0; pr < 4; pr++) {
                    mma16816(d[0][2*pr],   a0, bf[pr][0], bf[pr][1]);
                    mma16816(d[0][2*pr+1], a0, bf[pr][2], bf[pr][3]);
                    mma16816(d[1][2*pr],   a1, bf[pr][0], bf[pr][1]);
                    mma16816(d[1][2*pr+1], a1, bf[pr][2], bf[pr][3]);
                }
            }
        }

        // store prefetched x into next buffer, wait W, sync
        if (more) {
            uint4 h, l;
            split2(xv[0].x, xv[0].y, h.x, l.x); split2(xv[0].z, xv[0].w, h.y, l.y);
            split2(xv[1].x, xv[1].y, h.z, l.z); split2(xv[1].z, xv[1].w, h.w, l.w);
            *(uint4*)(nbufc + OFF_AH + xo0) = h;
            *(uint4*)(nbufc + OFF_AL + xo0) = l;
            split2(xv[2].x, xv[2].y, h.x, l.x); split2(xv[2].z, xv[2].w, h.y, l.y);
            split2(xv[3].x, xv[3].y, h.z, l.z); split2(xv[3].z, xv[3].w, h.w, l.w);
            *(uint4*)(nbufc + OFF_AH + xo1) = h;
            *(uint4*)(nbufc + OFF_AL + xo1) = l;
            cp_wait0();
        }
        __syncthreads();
    }

    // ---------------- epilogue ----------------
    // thread's values: rows mw*32 + mb*16 + lid/4 + rh*8 ; cols nw*64 + nb*8 + (lid&3)*2 + jj
    #pragma unroll
    for (int mb = 0; mb < 2; mb++) {
        #pragma unroll
        for (int rh = 0; rh < 2; rh++) {
            float v[16];
            float s0 = 0.f, q0 = 0.f, s1 = 0.f, q1 = 0.f;
            #pragma unroll
            for (int nb = 0; nb < 8; nb++) {
                #pragma unroll
                for (int jj = 0; jj < 2; jj++) {
                    int c = nw * 64 + nb * 8 + (lid & 3) * 2 + jj;
                    float val = d[mb][nb][rh * 2 + jj] + smf[SM_BL / 4 + c];
                    v[nb * 2 + jj] = val;
                    if (nb < 4) { s0 += val; q0 += val * val; }
                    else        { s1 += val; q1 += val * val; }
                }
            }
            s0 += __shfl_xor_sync(~0u, s0, 1); s0 += __shfl_xor_sync(~0u, s0, 2);
            q0 += __shfl_xor_sync(~0u, q0, 1); q0 += __shfl_xor_sync(~0u, q0, 2);
            s1 += __shfl_xor_sync(~0u, s1, 1); s1 += __shfl_xor_sync(~0u, s1, 2);
            q1 += __shfl_xor_sync(~0u, q1, 1); q1 += __shfl_xor_sync(~0u, q1, 2);
            float mean0 = s0 * (1.f / 32.f);
            float rstd0 = rsqrtf(q0 * (1.f / 32.f) - mean0 * mean0 + EPS);
            float mean1 = s1 * (1.f / 32.f);
            float rstd1 = rsqrtf(q1 * (1.f / 32.f) - mean1 * mean1 + EPS);

            float rmn = 3.4e38f;
            #pragma unroll
            for (int nb = 0; nb < 8; nb++) {
                float mu = (nb < 4) ? mean0 : mean1;
                float rs = (nb < 4) ? rstd0 : rstd1;
                #pragma unroll
                for (int jj = 0; jj < 2; jj++) {
                    int c = nw * 64 + nb * 8 + (lid & 3) * 2 + jj;
                    float g = (v[nb * 2 + jj] - mu) * rs * smf[SM_WGN / 4 + c]
                              + smf[SM_BGN / 4 + c];
                    rmn = fminf(rmn, g);
                }
            }
            rmn = fminf(rmn, __shfl_xor_sync(~0u, rmn, 1));
            rmn = fminf(rmn, __shfl_xor_sync(~0u, rmn, 2));
            if ((lid & 3) == 0) {
                int row = mw * 32 + mb * 16 + (lid >> 2) + rh * 8;
                smf[SM_ROWMIN / 4 + nw * 64 + row] = rmn;
            }
        }
    }
    __syncthreads();
    if (tid < 64) {
        float m = fminf(fminf(smf[SM_ROWMIN / 4 + tid],       smf[SM_ROWMIN / 4 + 64  + tid]),
                        fminf(smf[SM_ROWMIN / 4 + 128 + tid], smf[SM_ROWMIN / 4 + 192 + tid]));
        smf[SM_SMIN / 4 + tid] = m;
    }
    __syncthreads();

    // broadcast write: out[c*B + b] = min[b] + bias[c]
    {
        const int q  = tid & 15;
        const int cb = tid >> 4;
        float4 mv = *(const float4*)&smf[SM_SMIN / 4 + q * 4];
        #pragma unroll
        for (int i = 0; i < 16; i++) {
            int c = cb + i * 16;
            float bc = __ldg(bias + c);
            float4 o;
            o.x = mv.x + bc; o.y = mv.y + bc; o.z = mv.z + bc; o.w = mv.w + bc;
            *(float4*)(out + (size_t)c * BATCH + b0 + q * 4) = o;
        }
    }
}

extern "C" void kernel_launch(void* const* d_in, const int* in_sizes, int n_in,
                              void* d_out, int out_size) {
    const float* x  = (const float*)d_in[0];
    const float* W  = (const float*)d_in[1];
    const float* bl = (const float*)d_in[2];
    const float* wg = (const float*)d_in[3];
    const float* bg = (const float*)d_in[4];
    const float* bs = (const float*)d_in[5];
    float* out = (float*)d_out;

    cudaFuncSetAttribute(fused_mma_kernel,
                         cudaFuncAttributeMaxDynamicSharedMemorySize, SM_TOTAL);

    split_w_kernel<<<(OUT_FEAT * IN_FEAT) / 256, 256>>>(W);
    fused_mma_kernel<<<BATCH / BM, NTHREADS, SM_TOTAL>>>(x, bl, wg, bg, bs, out);
}